// round 8
// baseline (speedup 1.0000x reference)
#include <cuda_runtime.h>
#include <cuda_bf16.h>
#include <cuda_fp16.h>

// Problem constants (fixed by the reference)
#define BB 256
#define TT 1024
#define EE 32
#define HH 128
#define GG 512   // 4*H
#define SLOTS (BB * TT)

typedef unsigned long long u64;

// ---- f32x2 packed FMA (Blackwell FFMA2: only reachable via PTX) ----
__device__ __forceinline__ u64 ffma2(u64 a, u64 b, u64 c) {
    u64 d;
    asm("fma.rn.f32x2 %0, %1, %2, %3;" : "=l"(d) : "l"(a), "l"(b), "l"(c));
    return d;
}
__device__ __forceinline__ u64 packf2(float lo, float hi) {
    u64 d;
    asm("mov.b64 %0, {%1, %2};" : "=l"(d) : "f"(lo), "f"(hi));
    return d;
}
__device__ __forceinline__ float2 unpackf2(u64 v) {
    float2 r;
    asm("mov.b64 {%0, %1}, %2;" : "=f"(r.x), "=f"(r.y) : "l"(v));
    return r;
}

__device__ __forceinline__ float sigmoidf_fast(float x) {
    return 1.0f / (1.0f + __expf(-x));
}
__device__ __forceinline__ float tanhf_fast(float x) {
    return 2.0f / (1.0f + __expf(-2.0f * x)) - 1.0f;
}

// 512 MB scratch: precomputed x-projection gate_x[slot][512] = bias + x.Wih^T
__device__ float g_gx[(size_t)SLOTS * GG];

// ---------------------------------------------------------------------------
// Kernel 1: embedded[b,t,:] = is_action ? action_emb[action_ids] : 0
// ---------------------------------------------------------------------------
__global__ void embed_init_kernel(const int* __restrict__ action_ids,
                                  const int* __restrict__ is_action,
                                  const float* __restrict__ action_emb,
                                  float* __restrict__ emb) {
    int gid = blockIdx.x * blockDim.x + threadIdx.x;   // BB*TT*8 threads
    int slot = gid >> 3;
    int e4 = gid & 7;
    float4 v = make_float4(0.f, 0.f, 0.f, 0.f);
    if (is_action[slot]) {
        int aid = action_ids[slot];
        v = reinterpret_cast<const float4*>(action_emb + (size_t)aid * EE)[e4];
    }
    reinterpret_cast<float4*>(emb)[gid] = v;
}

// ---------------------------------------------------------------------------
// Kernel 2: ragged embedding-bag scatter: emb[slot] += obs_emb[id] if !is_action
// ---------------------------------------------------------------------------
__global__ void obs_scatter_kernel(const int* __restrict__ obs_ids,
                                   const int* __restrict__ obs_slot,
                                   const int* __restrict__ is_action,
                                   const float* __restrict__ obs_emb,
                                   float* __restrict__ emb,
                                   int n_threads) {
    int gid = blockIdx.x * blockDim.x + threadIdx.x;
    if (gid >= n_threads) return;
    int i = gid >> 3;
    int e4 = gid & 7;
    int slot = obs_slot[i];
    if (!is_action[slot]) {
        int id = obs_ids[i];
        float4 v = reinterpret_cast<const float4*>(obs_emb + (size_t)id * EE)[e4];
        float* dst = emb + (size_t)slot * EE + e4 * 4;
        atomicAdd(dst + 0, v.x);
        atomicAdd(dst + 1, v.y);
        atomicAdd(dst + 2, v.z);
        atomicAdd(dst + 3, v.w);
    }
}

// ---------------------------------------------------------------------------
// Kernel 3: gate_x pre-GEMM. gx[slot][j] = (b_ih+b_hh)[j] + emb[slot,:].Wih[j,:]
// ---------------------------------------------------------------------------
#define XCHUNK 64
__global__ void __launch_bounds__(256, 2)
gatex_kernel(const float* __restrict__ emb, const float* __restrict__ W_ih,
             const float* __restrict__ b_ih, const float* __restrict__ b_hh) {
    __shared__ float xs[XCHUNK * EE];    // 8 KB
    const int tid = threadIdx.x;
    const int j0 = tid;
    const int j1 = tid + 256;

    u64 w0[16], w1[16];
    {
        const ulonglong2* s0 = reinterpret_cast<const ulonglong2*>(W_ih + (size_t)j0 * EE);
        const ulonglong2* s1 = reinterpret_cast<const ulonglong2*>(W_ih + (size_t)j1 * EE);
        #pragma unroll
        for (int i = 0; i < 8; i++) {
            ulonglong2 a = s0[i]; w0[2*i] = a.x; w0[2*i+1] = a.y;
            ulonglong2 b = s1[i]; w1[2*i] = b.x; w1[2*i+1] = b.y;
        }
    }
    const float bias0 = b_ih[j0] + b_hh[j0];
    const float bias1 = b_ih[j1] + b_hh[j1];

    const int base = blockIdx.x * XCHUNK;

    {
        const float4* src = reinterpret_cast<const float4*>(emb + (size_t)base * EE);
        reinterpret_cast<float4*>(xs)[tid] = src[tid];
        reinterpret_cast<float4*>(xs)[tid + 256] = src[tid + 256];
    }
    __syncthreads();

    #pragma unroll 2
    for (int s = 0; s < XCHUNK; s++) {
        const ulonglong2* xv = reinterpret_cast<const ulonglong2*>(xs + s * EE);
        u64 a0 = 0ull, a1 = 0ull;
        #pragma unroll
        for (int k4 = 0; k4 < 8; k4++) {
            ulonglong2 x = xv[k4];
            a0 = ffma2(w0[2*k4],     x.x, a0);
            a0 = ffma2(w0[2*k4 + 1], x.y, a0);
            a1 = ffma2(w1[2*k4],     x.x, a1);
            a1 = ffma2(w1[2*k4 + 1], x.y, a1);
        }
        float2 r0 = unpackf2(a0);
        float2 r1 = unpackf2(a1);
        size_t o = (size_t)(base + s) * GG;
        g_gx[o + j0] = bias0 + r0.x + r0.y;
        g_gx[o + j1] = bias1 + r1.x + r1.y;
    }
}

// ---------------------------------------------------------------------------
// Kernel 4: persistent LSTM recurrence.
// Phase A (GEMM): 512 threads = 256 column-pairs x 2 k-halves. Thread (j2,q)
// computes partial gate dots for columns {j2, j2+256}, rows {0,1},
// k in [64q, 64q+64):
//   - k_local 0..47 (48 floats/col) in registers (24 u64 f32x2 per col)
//   - k_local 48..63 (16 floats/col) streamed from smem (8 LDS.128/step)
//   - h broadcast: only its own k-half (32 LDS.128/step)
// Partials land in P[tid] = float4(r0c0, r0c1, r1c0, r1c1).
//
// Phase B (pointwise): distributed over ALL 16 warps with lane pairing.
// Item (r, hc): warp w = item/16; lane l = item%16 computes (i,g); lane l+16
// computes (f,o); exchange via one shfl_down(16); lane<16 owns c/h and stores.
// Exact fp32 everywhere.
// ---------------------------------------------------------------------------
#define HELD_U64  24             // u64 per col in regs (k_local 0..47)
#define STR_QUADS 4              // float4 per col streamed (k_local 48..63)

#define OFF_WS 0
#define SZ_WS  (2 * STR_QUADS * 512 * 16)    // 65536
#define OFF_H  (OFF_WS + SZ_WS)
#define SZ_H   (2 * HH * 4)                  // 1024
#define OFF_P  (OFF_H + SZ_H)
#define SZ_P   (512 * 16)                    // 8192
#define SMEM_TOTAL (OFF_P + SZ_P)            // 74752

__global__ void __launch_bounds__(512, 1)
lstm_kernel(const float* __restrict__ W_hh,
            const int* __restrict__ lengths,
            float* __restrict__ outs,           // [B,T,H]
            float* __restrict__ h_out,          // [B,H]
            float* __restrict__ c_out) {        // [B,H]
    extern __shared__ char smem[];
    float4* WS  = reinterpret_cast<float4*>(smem + OFF_WS);   // [2*4][512]
    float*  h_s = reinterpret_cast<float*>(smem + OFF_H);     // [2][128]
    float4* P   = reinterpret_cast<float4*>(smem + OFF_P);    // [512]

    const int tid = threadIdx.x;
    const int j2  = tid & 255;
    const int q   = tid >> 8;          // k-half (warp-uniform)
    const int b0  = blockIdx.x * 2;
    const int col0 = j2;
    const int col1 = j2 + 256;
    const int kbase = q * 64;

    // ---- one-time weight staging ----
    // wa[0..23] = col0 (k_local 0..47), wa[24..47] = col1 (k_local 0..47)
    u64 wa[2 * HELD_U64];
    {
        const ulonglong2* s0 = reinterpret_cast<const ulonglong2*>(W_hh + (size_t)col0 * HH + kbase);
        const ulonglong2* s1 = reinterpret_cast<const ulonglong2*>(W_hh + (size_t)col1 * HH + kbase);
        #pragma unroll
        for (int i = 0; i < HELD_U64 / 2; i++) {     // 12 x 16B per col
            ulonglong2 a = s0[i]; wa[2*i] = a.x; wa[2*i+1] = a.y;
            ulonglong2 b = s1[i]; wa[HELD_U64 + 2*i] = b.x; wa[HELD_U64 + 2*i+1] = b.y;
        }
        // streamed region: k_local 48..63 (= 2*HELD_U64 floats in)
        const float4* t0 = reinterpret_cast<const float4*>(W_hh + (size_t)col0 * HH + kbase + 2 * HELD_U64);
        const float4* t1 = reinterpret_cast<const float4*>(W_hh + (size_t)col1 * HH + kbase + 2 * HELD_U64);
        #pragma unroll
        for (int i = 0; i < STR_QUADS; i++) {
            WS[i * 512 + tid] = t0[i];
            WS[(STR_QUADS + i) * 512 + tid] = t1[i];
        }
    }
    if (tid < 2 * HH) h_s[tid] = 0.f;

    // ---- phase-B role: warp w, lane l; item = w*16 + (l & 15) ----
    const int w = tid >> 5;
    const int l = tid & 31;
    const int item = (w << 4) + (l & 15);
    const int r  = item >> 7;          // warp-uniform row (warps 0-7: r=0)
    const int hc = item & 127;
    const bool ig = (l < 16);          // lanes 0-15: gates (i,g); 16-31: (f,o)
    const int len = lengths[b0 + r];
    float c_reg = 0.f, h_reg = 0.f;

    // gx columns: ig -> {hc, 256+hc} = (i,g); fo -> {128+hc, 384+hc} = (f,o)
    const int goff = (ig ? 0 : 128) + hc;
    const float* gxp = g_gx + ((size_t)(b0 + r) * TT) * GG;
    float gxa = __ldg(gxp + goff);
    float gxb = __ldg(gxp + goff + 256);

    // P gather source: column-pair index (j2 of producer), component offset 2r
    const int pidx = goff;             // same col-pair index as gx columns
    const float* Pf = reinterpret_cast<const float*>(P);

    const ulonglong2* h2 = reinterpret_cast<const ulonglong2*>(h_s);  // 64 quads
    const ulonglong2* WSu = reinterpret_cast<const ulonglong2*>(WS);
    const int hoff = q * 16;

    for (int t = 0; t < TT; t++) {
        __syncthreads();   // S0: h_s(t-1) final, P(t-1) consumed

        // ---- phase A: partial dots over this thread's k-half ----
        u64 a00 = 0ull, a01 = 0ull, a10 = 0ull, a11 = 0ull;  // a[row][colpair]
        #pragma unroll
        for (int i = 0; i < HELD_U64 / 2; i++) {             // k_local 0..47
            ulonglong2 h0 = h2[hoff + i];
            ulonglong2 h1 = h2[32 + hoff + i];
            u64 wc0a = wa[2*i],             wc0b = wa[2*i + 1];
            u64 wc1a = wa[HELD_U64 + 2*i],  wc1b = wa[HELD_U64 + 2*i + 1];
            a00 = ffma2(wc0a, h0.x, a00); a00 = ffma2(wc0b, h0.y, a00);
            a01 = ffma2(wc1a, h0.x, a01); a01 = ffma2(wc1b, h0.y, a01);
            a10 = ffma2(wc0a, h1.x, a10); a10 = ffma2(wc0b, h1.y, a10);
            a11 = ffma2(wc1a, h1.x, a11); a11 = ffma2(wc1b, h1.y, a11);
        }
        #pragma unroll
        for (int i = 0; i < STR_QUADS; i++) {                // k_local 48..63
            ulonglong2 s0 = WSu[i * 512 + tid];
            ulonglong2 s1 = WSu[(STR_QUADS + i) * 512 + tid];
            ulonglong2 h0 = h2[hoff + HELD_U64 / 2 + i];
            ulonglong2 h1 = h2[32 + hoff + HELD_U64 / 2 + i];
            a00 = ffma2(s0.x, h0.x, a00); a00 = ffma2(s0.y, h0.y, a00);
            a01 = ffma2(s1.x, h0.x, a01); a01 = ffma2(s1.y, h0.y, a01);
            a10 = ffma2(s0.x, h1.x, a10); a10 = ffma2(s0.y, h1.y, a10);
            a11 = ffma2(s1.x, h1.x, a11); a11 = ffma2(s1.y, h1.y, a11);
        }
        float2 f00 = unpackf2(a00), f01 = unpackf2(a01);
        float2 f10 = unpackf2(a10), f11 = unpackf2(a11);
        P[tid] = make_float4(f00.x + f00.y,    // (row0, col0)
                             f01.x + f01.y,    // (row0, col1)
                             f10.x + f10.y,    // (row1, col0)
                             f11.x + f11.y);   // (row1, col1)

        __syncthreads();   // S1: partials ready

        // ---- phase B: distributed pointwise (all 16 warps, lane-paired) ----
        // gate sums for this lane's 2 gates: q=0 partial + q=1 partial + gx
        float2 A = *reinterpret_cast<const float2*>(Pf + pidx * 4 + 2 * r);
        float2 Bv = *reinterpret_cast<const float2*>(Pf + (256 + pidx) * 4 + 2 * r);
        float ga = A.x + Bv.x + gxa;     // i (ig) or f (fo)
        float gb = A.y + Bv.y + gxb;     // g (ig) or o (fo)
        float va = sigmoidf_fast(ga);
        float vb = ig ? tanhf_fast(gb) : sigmoidf_fast(gb);
        u64 pk = packf2(va, vb);
        u64 other = __shfl_down_sync(0xffffffffu, pk, 16);
        if (ig) {
            float2 fo = unpackf2(other);                // (f_, o_)
            float cn = fmaf(fo.x, c_reg, va * vb);      // f*c + i*g
            float hn = fo.y * tanhf_fast(cn);
            bool m = (t < len);
            h_reg = m ? hn : h_reg;
            c_reg = m ? cn : c_reg;
            h_s[r * HH + hc] = h_reg;
            outs[((size_t)(b0 + r) * TT + t) * HH + hc] = m ? hn : 0.f;
        }
        // prefetch gx(t+1) — hidden behind next phase A
        if (t + 1 < TT) {
            const float* gn = gxp + (size_t)(t + 1) * GG;
            gxa = __ldg(gn + goff);
            gxb = __ldg(gn + goff + 256);
        }
    }

    if (ig) {
        h_out[(size_t)(b0 + r) * HH + hc] = h_reg;
        c_out[(size_t)(b0 + r) * HH + hc] = c_reg;
    }
}

// ---------------------------------------------------------------------------
// kernel_launch — graph-capturable: 4 launches on the default stream.
// Output: outputs[B,T,H] | h[1,B,H] | c[1,B,H] | embedded[B,T,E]
// ---------------------------------------------------------------------------
extern "C" void kernel_launch(void* const* d_in, const int* in_sizes, int n_in,
                              void* d_out, int out_size) {
    const int*   obs_ids     = (const int*)d_in[0];
    const int*   obs_slot    = (const int*)d_in[1];
    const int*   action_ids  = (const int*)d_in[2];
    const int*   is_action   = (const int*)d_in[3];
    const int*   lengths     = (const int*)d_in[4];
    const float* action_emb  = (const float*)d_in[5];
    const float* obs_emb     = (const float*)d_in[6];
    const float* W_ih        = (const float*)d_in[7];
    const float* W_hh        = (const float*)d_in[8];
    const float* b_ih        = (const float*)d_in[9];
    const float* b_hh        = (const float*)d_in[10];

    float* out   = (float*)d_out;
    float* outs  = out;                                    // B*T*H
    float* h_out = out + (size_t)BB * TT * HH;             // B*H
    float* c_out = h_out + (size_t)BB * HH;                // B*H
    float* emb   = c_out + (size_t)BB * HH;                // B*T*E

    cudaFuncSetAttribute(lstm_kernel,
                         cudaFuncAttributeMaxDynamicSharedMemorySize, SMEM_TOTAL);

    // 1) embedded = is_action ? action_emb[aid] : 0
    {
        int nthreads = BB * TT * 8;
        embed_init_kernel<<<nthreads / 256, 256>>>(action_ids, is_action,
                                                   action_emb, emb);
    }
    // 2) scatter-add observation embeddings into non-action slots
    {
        int n_obs = in_sizes[0];
        int nthreads = n_obs * 8;
        int blocks = (nthreads + 255) / 256;
        obs_scatter_kernel<<<blocks, 256>>>(obs_ids, obs_slot, is_action,
                                            obs_emb, emb, nthreads);
    }
    // 3) x-projection pre-GEMM: gx = bias + emb @ Wih^T  (262144 x 512)
    gatex_kernel<<<SLOTS / XCHUNK, 256>>>(emb, W_ih, b_ih, b_hh);

    // 4) persistent LSTM recurrence: 128 CTAs x 512 threads, 1 CTA/SM
    lstm_kernel<<<BB / 2, 512, SMEM_TOTAL>>>(W_hh, lengths, outs, h_out, c_out);
}

// round 9
// speedup vs baseline: 1.1292x; 1.1292x over previous
#include <cuda_runtime.h>
#include <cuda_bf16.h>
#include <cuda_fp16.h>

// Problem constants (fixed by the reference)
#define BB 256
#define TT 1024
#define EE 32
#define HH 128
#define GG 512   // 4*H
#define SLOTS (BB * TT)

typedef unsigned long long u64;

// ---- f32x2 packed FMA (Blackwell FFMA2: only reachable via PTX) ----
__device__ __forceinline__ u64 ffma2(u64 a, u64 b, u64 c) {
    u64 d;
    asm("fma.rn.f32x2 %0, %1, %2, %3;" : "=l"(d) : "l"(a), "l"(b), "l"(c));
    return d;
}
__device__ __forceinline__ u64 packf2(float lo, float hi) {
    u64 d;
    asm("mov.b64 %0, {%1, %2};" : "=l"(d) : "f"(lo), "f"(hi));
    return d;
}
__device__ __forceinline__ float2 unpackf2(u64 v) {
    float2 r;
    asm("mov.b64 {%0, %1}, %2;" : "=f"(r.x), "=f"(r.y) : "l"(v));
    return r;
}

__device__ __forceinline__ float sigmoidf_fast(float x) {
    return 1.0f / (1.0f + __expf(-x));
}
__device__ __forceinline__ float tanhf_fast(float x) {
    return 2.0f / (1.0f + __expf(-2.0f * x)) - 1.0f;
}

// 512 MB scratch: precomputed x-projection gate_x[slot][512] = bias + x.Wih^T
__device__ float g_gx[(size_t)SLOTS * GG];

// ---------------------------------------------------------------------------
// Kernel 1: embedded[b,t,:] = is_action ? action_emb[action_ids] : 0
// ---------------------------------------------------------------------------
__global__ void embed_init_kernel(const int* __restrict__ action_ids,
                                  const int* __restrict__ is_action,
                                  const float* __restrict__ action_emb,
                                  float* __restrict__ emb) {
    int gid = blockIdx.x * blockDim.x + threadIdx.x;   // BB*TT*8 threads
    int slot = gid >> 3;
    int e4 = gid & 7;
    float4 v = make_float4(0.f, 0.f, 0.f, 0.f);
    if (is_action[slot]) {
        int aid = action_ids[slot];
        v = reinterpret_cast<const float4*>(action_emb + (size_t)aid * EE)[e4];
    }
    reinterpret_cast<float4*>(emb)[gid] = v;
}

// ---------------------------------------------------------------------------
// Kernel 2: ragged embedding-bag scatter: emb[slot] += obs_emb[id] if !is_action
// ---------------------------------------------------------------------------
__global__ void obs_scatter_kernel(const int* __restrict__ obs_ids,
                                   const int* __restrict__ obs_slot,
                                   const int* __restrict__ is_action,
                                   const float* __restrict__ obs_emb,
                                   float* __restrict__ emb,
                                   int n_threads) {
    int gid = blockIdx.x * blockDim.x + threadIdx.x;
    if (gid >= n_threads) return;
    int i = gid >> 3;
    int e4 = gid & 7;
    int slot = obs_slot[i];
    if (!is_action[slot]) {
        int id = obs_ids[i];
        float4 v = reinterpret_cast<const float4*>(obs_emb + (size_t)id * EE)[e4];
        float* dst = emb + (size_t)slot * EE + e4 * 4;
        atomicAdd(dst + 0, v.x);
        atomicAdd(dst + 1, v.y);
        atomicAdd(dst + 2, v.z);
        atomicAdd(dst + 3, v.w);
    }
}

// ---------------------------------------------------------------------------
// Kernel 3: gate_x pre-GEMM. gx[slot][j] = (b_ih+b_hh)[j] + emb[slot,:].Wih[j,:]
// ---------------------------------------------------------------------------
#define XCHUNK 64
__global__ void __launch_bounds__(256, 2)
gatex_kernel(const float* __restrict__ emb, const float* __restrict__ W_ih,
             const float* __restrict__ b_ih, const float* __restrict__ b_hh) {
    __shared__ float xs[XCHUNK * EE];    // 8 KB
    const int tid = threadIdx.x;
    const int j0 = tid;
    const int j1 = tid + 256;

    u64 w0[16], w1[16];
    {
        const ulonglong2* s0 = reinterpret_cast<const ulonglong2*>(W_ih + (size_t)j0 * EE);
        const ulonglong2* s1 = reinterpret_cast<const ulonglong2*>(W_ih + (size_t)j1 * EE);
        #pragma unroll
        for (int i = 0; i < 8; i++) {
            ulonglong2 a = s0[i]; w0[2*i] = a.x; w0[2*i+1] = a.y;
            ulonglong2 b = s1[i]; w1[2*i] = b.x; w1[2*i+1] = b.y;
        }
    }
    const float bias0 = b_ih[j0] + b_hh[j0];
    const float bias1 = b_ih[j1] + b_hh[j1];

    const int base = blockIdx.x * XCHUNK;

    {
        const float4* src = reinterpret_cast<const float4*>(emb + (size_t)base * EE);
        reinterpret_cast<float4*>(xs)[tid] = src[tid];
        reinterpret_cast<float4*>(xs)[tid + 256] = src[tid + 256];
    }
    __syncthreads();

    #pragma unroll 2
    for (int s = 0; s < XCHUNK; s++) {
        const ulonglong2* xv = reinterpret_cast<const ulonglong2*>(xs + s * EE);
        u64 a0 = 0ull, a1 = 0ull;
        #pragma unroll
        for (int k4 = 0; k4 < 8; k4++) {
            ulonglong2 x = xv[k4];
            a0 = ffma2(w0[2*k4],     x.x, a0);
            a0 = ffma2(w0[2*k4 + 1], x.y, a0);
            a1 = ffma2(w1[2*k4],     x.x, a1);
            a1 = ffma2(w1[2*k4 + 1], x.y, a1);
        }
        float2 r0 = unpackf2(a0);
        float2 r1 = unpackf2(a1);
        size_t o = (size_t)(base + s) * GG;
        g_gx[o + j0] = bias0 + r0.x + r0.y;
        g_gx[o + j1] = bias1 + r1.x + r1.y;
    }
}

// ---------------------------------------------------------------------------
// Kernel 4: persistent LSTM recurrence.
// Phase A (GEMM) — R6's proven register budget:
//   512 threads = 256 column-pairs x 2 k-halves. Thread (j2,q) computes
//   partial gate dots for columns {j2, j2+256}, rows {0,1}, k in [64q,64q+64):
//   - k_local 0..39 (40 floats/col = 20 u64/col, 80 regs total) in registers
//   - k_local 40..63 (24 floats/col) streamed from smem (12 LDS.128/step)
//   - h broadcast: only its own k-half (32 LDS.128/step)
//   Partials land in P[tid] = float4(r0c0, r0c1, r1c0, r1c1).
//
// Phase B (pointwise) — distributed over ALL 16 warps with lane pairing:
//   Item (r,hc): warp w = item/16; lane l = item%16 computes (i,g); lane l+16
//   computes (f,o); exchange via one shfl_down(16); lane<16 owns c/h, stores.
// Exact fp32 everywhere.
// ---------------------------------------------------------------------------
#define HELD_U64  20             // u64 per col in regs (k_local 0..39) — R6 budget
#define STR_QUADS 6              // float4 per col streamed (k_local 40..63)

#define OFF_WS 0
#define SZ_WS  (2 * STR_QUADS * 512 * 16)    // 98304
#define OFF_H  (OFF_WS + SZ_WS)
#define SZ_H   (2 * HH * 4)                  // 1024
#define OFF_P  (OFF_H + SZ_H)
#define SZ_P   (512 * 16)                    // 8192
#define SMEM_TOTAL (OFF_P + SZ_P)            // 107520

__global__ void __launch_bounds__(512, 1)
lstm_kernel(const float* __restrict__ W_hh,
            const int* __restrict__ lengths,
            float* __restrict__ outs,           // [B,T,H]
            float* __restrict__ h_out,          // [B,H]
            float* __restrict__ c_out) {        // [B,H]
    extern __shared__ char smem[];
    float4* WS  = reinterpret_cast<float4*>(smem + OFF_WS);   // [2*6][512]
    float*  h_s = reinterpret_cast<float*>(smem + OFF_H);     // [2][128]
    float4* P   = reinterpret_cast<float4*>(smem + OFF_P);    // [512]

    const int tid = threadIdx.x;
    const int j2  = tid & 255;
    const int q   = tid >> 8;          // k-half (warp-uniform)
    const int b0  = blockIdx.x * 2;
    const int col0 = j2;
    const int col1 = j2 + 256;
    const int kbase = q * 64;

    // ---- one-time weight staging ----
    // wa[0..19] = col0 (k_local 0..39), wa[20..39] = col1 (k_local 0..39)
    u64 wa[2 * HELD_U64];
    {
        const ulonglong2* s0 = reinterpret_cast<const ulonglong2*>(W_hh + (size_t)col0 * HH + kbase);
        const ulonglong2* s1 = reinterpret_cast<const ulonglong2*>(W_hh + (size_t)col1 * HH + kbase);
        #pragma unroll
        for (int i = 0; i < HELD_U64 / 2; i++) {     // 10 x 16B per col
            ulonglong2 a = s0[i]; wa[2*i] = a.x; wa[2*i+1] = a.y;
            ulonglong2 b = s1[i]; wa[HELD_U64 + 2*i] = b.x; wa[HELD_U64 + 2*i+1] = b.y;
        }
        // streamed region: k_local 40..63 (= 2*HELD_U64 floats in)
        const float4* t0 = reinterpret_cast<const float4*>(W_hh + (size_t)col0 * HH + kbase + 2 * HELD_U64);
        const float4* t1 = reinterpret_cast<const float4*>(W_hh + (size_t)col1 * HH + kbase + 2 * HELD_U64);
        #pragma unroll
        for (int i = 0; i < STR_QUADS; i++) {
            WS[i * 512 + tid] = t0[i];
            WS[(STR_QUADS + i) * 512 + tid] = t1[i];
        }
    }
    if (tid < 2 * HH) h_s[tid] = 0.f;

    // ---- phase-B role: warp w, lane l; item = w*16 + (l & 15) ----
    const int w = tid >> 5;
    const int l = tid & 31;
    const int item = (w << 4) + (l & 15);
    const int r  = item >> 7;          // warp-uniform row (warps 0-7: r=0)
    const int hc = item & 127;
    const bool ig = (l < 16);          // lanes 0-15: gates (i,g); 16-31: (f,o)
    const int len = lengths[b0 + r];
    float c_reg = 0.f, h_reg = 0.f;

    // gx columns: ig -> {hc, 256+hc} = (i,g); fo -> {128+hc, 384+hc} = (f,o)
    const int goff = (ig ? 0 : 128) + hc;
    const float* gxp = g_gx + ((size_t)(b0 + r) * TT) * GG;
    float gxa = __ldg(gxp + goff);
    float gxb = __ldg(gxp + goff + 256);

    // P gather source: producer column-pair index == goff, component 2r
    const int pidx = goff;
    const float* Pf = reinterpret_cast<const float*>(P);

    const ulonglong2* h2 = reinterpret_cast<const ulonglong2*>(h_s);  // 64 quads
    const ulonglong2* WSu = reinterpret_cast<const ulonglong2*>(WS);
    const int hoff = q * 16;

    for (int t = 0; t < TT; t++) {
        __syncthreads();   // S0: h_s(t-1) final, P(t-1) consumed

        // ---- phase A: partial dots over this thread's k-half ----
        u64 a00 = 0ull, a01 = 0ull, a10 = 0ull, a11 = 0ull;  // a[row][colpair]
        #pragma unroll
        for (int i = 0; i < HELD_U64 / 2; i++) {             // k_local 0..39
            ulonglong2 h0 = h2[hoff + i];
            ulonglong2 h1 = h2[32 + hoff + i];
            u64 wc0a = wa[2*i],             wc0b = wa[2*i + 1];
            u64 wc1a = wa[HELD_U64 + 2*i],  wc1b = wa[HELD_U64 + 2*i + 1];
            a00 = ffma2(wc0a, h0.x, a00); a00 = ffma2(wc0b, h0.y, a00);
            a01 = ffma2(wc1a, h0.x, a01); a01 = ffma2(wc1b, h0.y, a01);
            a10 = ffma2(wc0a, h1.x, a10); a10 = ffma2(wc0b, h1.y, a10);
            a11 = ffma2(wc1a, h1.x, a11); a11 = ffma2(wc1b, h1.y, a11);
        }
        #pragma unroll
        for (int i = 0; i < STR_QUADS; i++) {                // k_local 40..63
            ulonglong2 s0 = WSu[i * 512 + tid];
            ulonglong2 s1 = WSu[(STR_QUADS + i) * 512 + tid];
            ulonglong2 h0 = h2[hoff + HELD_U64 / 2 + i];
            ulonglong2 h1 = h2[32 + hoff + HELD_U64 / 2 + i];
            a00 = ffma2(s0.x, h0.x, a00); a00 = ffma2(s0.y, h0.y, a00);
            a01 = ffma2(s1.x, h0.x, a01); a01 = ffma2(s1.y, h0.y, a01);
            a10 = ffma2(s0.x, h1.x, a10); a10 = ffma2(s0.y, h1.y, a10);
            a11 = ffma2(s1.x, h1.x, a11); a11 = ffma2(s1.y, h1.y, a11);
        }
        float2 f00 = unpackf2(a00), f01 = unpackf2(a01);
        float2 f10 = unpackf2(a10), f11 = unpackf2(a11);
        P[tid] = make_float4(f00.x + f00.y,    // (row0, col0)
                             f01.x + f01.y,    // (row0, col1)
                             f10.x + f10.y,    // (row1, col0)
                             f11.x + f11.y);   // (row1, col1)

        __syncthreads();   // S1: partials ready

        // ---- phase B: distributed pointwise (all 16 warps, lane-paired) ----
        float2 A  = *reinterpret_cast<const float2*>(Pf + pidx * 4 + 2 * r);
        float2 Bv = *reinterpret_cast<const float2*>(Pf + (256 + pidx) * 4 + 2 * r);
        float ga = A.x + Bv.x + gxa;     // i (ig) or f (fo)
        float gb = A.y + Bv.y + gxb;     // g (ig) or o (fo)
        float va = sigmoidf_fast(ga);
        float vb = ig ? tanhf_fast(gb) : sigmoidf_fast(gb);
        u64 pk = packf2(va, vb);
        u64 other = __shfl_down_sync(0xffffffffu, pk, 16);
        if (ig) {
            float2 fo = unpackf2(other);                // (f_, o_)
            float cn = fmaf(fo.x, c_reg, va * vb);      // f*c + i*g
            float hn = fo.y * tanhf_fast(cn);
            bool m = (t < len);
            h_reg = m ? hn : h_reg;
            c_reg = m ? cn : c_reg;
            h_s[r * HH + hc] = h_reg;
            outs[((size_t)(b0 + r) * TT + t) * HH + hc] = m ? hn : 0.f;
        }
        // prefetch gx(t+1) — hidden behind next phase A
        if (t + 1 < TT) {
            const float* gn = gxp + (size_t)(t + 1) * GG;
            gxa = __ldg(gn + goff);
            gxb = __ldg(gn + goff + 256);
        }
    }

    if (ig) {
        h_out[(size_t)(b0 + r) * HH + hc] = h_reg;
        c_out[(size_t)(b0 + r) * HH + hc] = c_reg;
    }
}

// ---------------------------------------------------------------------------
// kernel_launch — graph-capturable: 4 launches on the default stream.
// Output: outputs[B,T,H] | h[1,B,H] | c[1,B,H] | embedded[B,T,E]
// ---------------------------------------------------------------------------
extern "C" void kernel_launch(void* const* d_in, const int* in_sizes, int n_in,
                              void* d_out, int out_size) {
    const int*   obs_ids     = (const int*)d_in[0];
    const int*   obs_slot    = (const int*)d_in[1];
    const int*   action_ids  = (const int*)d_in[2];
    const int*   is_action   = (const int*)d_in[3];
    const int*   lengths     = (const int*)d_in[4];
    const float* action_emb  = (const float*)d_in[5];
    const float* obs_emb     = (const float*)d_in[6];
    const float* W_ih        = (const float*)d_in[7];
    const float* W_hh        = (const float*)d_in[8];
    const float* b_ih        = (const float*)d_in[9];
    const float* b_hh        = (const float*)d_in[10];

    float* out   = (float*)d_out;
    float* outs  = out;                                    // B*T*H
    float* h_out = out + (size_t)BB * TT * HH;             // B*H
    float* c_out = h_out + (size_t)BB * HH;                // B*H
    float* emb   = c_out + (size_t)BB * HH;                // B*T*E

    cudaFuncSetAttribute(lstm_kernel,
                         cudaFuncAttributeMaxDynamicSharedMemorySize, SMEM_TOTAL);

    // 1) embedded = is_action ? action_emb[aid] : 0
    {
        int nthreads = BB * TT * 8;
        embed_init_kernel<<<nthreads / 256, 256>>>(action_ids, is_action,
                                                   action_emb, emb);
    }
    // 2) scatter-add observation embeddings into non-action slots
    {
        int n_obs = in_sizes[0];
        int nthreads = n_obs * 8;
        int blocks = (nthreads + 255) / 256;
        obs_scatter_kernel<<<blocks, 256>>>(obs_ids, obs_slot, is_action,
                                            obs_emb, emb, nthreads);
    }
    // 3) x-projection pre-GEMM: gx = bias + emb @ Wih^T  (262144 x 512)
    gatex_kernel<<<SLOTS / XCHUNK, 256>>>(emb, W_ih, b_ih, b_hh);

    // 4) persistent LSTM recurrence: 128 CTAs x 512 threads, 1 CTA/SM
    lstm_kernel<<<BB / 2, 512, SMEM_TOTAL>>>(W_hh, lengths, outs, h_out, c_out);
}

// round 10
// speedup vs baseline: 1.4378x; 1.2733x over previous
#include <cuda_runtime.h>
#include <cuda_bf16.h>
#include <cuda_fp16.h>

// Problem constants (fixed by the reference)
#define BB 256
#define TT 1024
#define EE 32
#define HH 128
#define GG 512   // 4*H
#define SLOTS (BB * TT)

typedef unsigned long long u64;

// ---- f32x2 packed FMA (Blackwell FFMA2: only reachable via PTX) ----
__device__ __forceinline__ u64 ffma2(u64 a, u64 b, u64 c) {
    u64 d;
    asm("fma.rn.f32x2 %0, %1, %2, %3;" : "=l"(d) : "l"(a), "l"(b), "l"(c));
    return d;
}
__device__ __forceinline__ float2 unpackf2(u64 v) {
    float2 r;
    asm("mov.b64 {%0, %1}, %2;" : "=f"(r.x), "=f"(r.y) : "l"(v));
    return r;
}

__device__ __forceinline__ float sigmoidf_fast(float x) {
    return 1.0f / (1.0f + __expf(-x));
}
__device__ __forceinline__ float tanhf_fast(float x) {
    return 2.0f / (1.0f + __expf(-2.0f * x)) - 1.0f;
}

// 512 MB scratch: precomputed x-projection gate_x[slot][512] = bias + x.Wih^T
__device__ float g_gx[(size_t)SLOTS * GG];

// ---------------------------------------------------------------------------
// Kernel 1: embedded[b,t,:] = is_action ? action_emb[action_ids] : 0
// ---------------------------------------------------------------------------
__global__ void embed_init_kernel(const int* __restrict__ action_ids,
                                  const int* __restrict__ is_action,
                                  const float* __restrict__ action_emb,
                                  float* __restrict__ emb) {
    int gid = blockIdx.x * blockDim.x + threadIdx.x;   // BB*TT*8 threads
    int slot = gid >> 3;
    int e4 = gid & 7;
    float4 v = make_float4(0.f, 0.f, 0.f, 0.f);
    if (is_action[slot]) {
        int aid = action_ids[slot];
        v = reinterpret_cast<const float4*>(action_emb + (size_t)aid * EE)[e4];
    }
    reinterpret_cast<float4*>(emb)[gid] = v;
}

// ---------------------------------------------------------------------------
// Kernel 2: ragged embedding-bag scatter: emb[slot] += obs_emb[id] if !is_action
// ---------------------------------------------------------------------------
__global__ void obs_scatter_kernel(const int* __restrict__ obs_ids,
                                   const int* __restrict__ obs_slot,
                                   const int* __restrict__ is_action,
                                   const float* __restrict__ obs_emb,
                                   float* __restrict__ emb,
                                   int n_threads) {
    int gid = blockIdx.x * blockDim.x + threadIdx.x;
    if (gid >= n_threads) return;
    int i = gid >> 3;
    int e4 = gid & 7;
    int slot = obs_slot[i];
    if (!is_action[slot]) {
        int id = obs_ids[i];
        float4 v = reinterpret_cast<const float4*>(obs_emb + (size_t)id * EE)[e4];
        float* dst = emb + (size_t)slot * EE + e4 * 4;
        atomicAdd(dst + 0, v.x);
        atomicAdd(dst + 1, v.y);
        atomicAdd(dst + 2, v.z);
        atomicAdd(dst + 3, v.w);
    }
}

// ---------------------------------------------------------------------------
// Kernel 3: gate_x pre-GEMM. gx[slot][j] = (b_ih+b_hh)[j] + emb[slot,:].Wih[j,:]
// ---------------------------------------------------------------------------
#define XCHUNK 64
__global__ void __launch_bounds__(256, 2)
gatex_kernel(const float* __restrict__ emb, const float* __restrict__ W_ih,
             const float* __restrict__ b_ih, const float* __restrict__ b_hh) {
    __shared__ float xs[XCHUNK * EE];    // 8 KB
    const int tid = threadIdx.x;
    const int j0 = tid;
    const int j1 = tid + 256;

    u64 w0[16], w1[16];
    {
        const ulonglong2* s0 = reinterpret_cast<const ulonglong2*>(W_ih + (size_t)j0 * EE);
        const ulonglong2* s1 = reinterpret_cast<const ulonglong2*>(W_ih + (size_t)j1 * EE);
        #pragma unroll
        for (int i = 0; i < 8; i++) {
            ulonglong2 a = s0[i]; w0[2*i] = a.x; w0[2*i+1] = a.y;
            ulonglong2 b = s1[i]; w1[2*i] = b.x; w1[2*i+1] = b.y;
        }
    }
    const float bias0 = b_ih[j0] + b_hh[j0];
    const float bias1 = b_ih[j1] + b_hh[j1];

    const int base = blockIdx.x * XCHUNK;

    {
        const float4* src = reinterpret_cast<const float4*>(emb + (size_t)base * EE);
        reinterpret_cast<float4*>(xs)[tid] = src[tid];
        reinterpret_cast<float4*>(xs)[tid + 256] = src[tid + 256];
    }
    __syncthreads();

    #pragma unroll 2
    for (int s = 0; s < XCHUNK; s++) {
        const ulonglong2* xv = reinterpret_cast<const ulonglong2*>(xs + s * EE);
        u64 a0 = 0ull, a1 = 0ull;
        #pragma unroll
        for (int k4 = 0; k4 < 8; k4++) {
            ulonglong2 x = xv[k4];
            a0 = ffma2(w0[2*k4],     x.x, a0);
            a0 = ffma2(w0[2*k4 + 1], x.y, a0);
            a1 = ffma2(w1[2*k4],     x.x, a1);
            a1 = ffma2(w1[2*k4 + 1], x.y, a1);
        }
        float2 r0 = unpackf2(a0);
        float2 r1 = unpackf2(a1);
        size_t o = (size_t)(base + s) * GG;
        g_gx[o + j0] = bias0 + r0.x + r0.y;
        g_gx[o + j1] = bias1 + r1.x + r1.y;
    }
}

// ---------------------------------------------------------------------------
// Kernel 4: persistent LSTM recurrence (R6 structure, + early exit at the
// CTA's max length, + mixed 1-row/2-row CTAs so the longest sequences run on
// faster 1-row CTAs and the grid fills all SMs in one wave).
//
// Phase A (GEMM), per thread (j2, q): columns {j2, j2+256}, k in [64q,64q+64):
//   - k_local 0..39 in registers (20 u64/col), k_local 40..63 streamed from
//     smem (12 LDS.128/step), h broadcast from smem (k-half only).
// Phase B (pointwise): threads (j2<128, q<NR) finalize item (row=q, hc=j2)
// by gathering partner partials from P; c/h in registers. Exact fp32.
// ---------------------------------------------------------------------------
#define HELD_U64  20             // u64 per col in regs (k_local 0..39)
#define STR_QUADS 6              // float4 per col streamed (k_local 40..63)

#define OFF_WS 0
#define SZ_WS  (2 * STR_QUADS * 512 * 16)    // 98304
#define OFF_H  (OFF_WS + SZ_WS)
#define SZ_H   (2 * HH * 4)                  // 1024
#define OFF_P  (OFF_H + SZ_H)
#define SZ_P   (512 * 16)                    // 8192
#define SMEM_TOTAL (OFF_P + SZ_P)            // 107520

template <int NR>
__device__ __forceinline__ void lstm_run(
    int b0, char* smem,
    const float* __restrict__ W_hh, const int* __restrict__ lengths,
    float* __restrict__ outs, float* __restrict__ h_out,
    float* __restrict__ c_out) {

    float4* WS  = reinterpret_cast<float4*>(smem + OFF_WS);   // [2*6][512]
    float*  h_s = reinterpret_cast<float*>(smem + OFF_H);     // [2][128]
    float4* P   = reinterpret_cast<float4*>(smem + OFF_P);    // [512]

    const int tid = threadIdx.x;
    const int j2  = tid & 255;
    const int q   = tid >> 8;          // k-half (warp-uniform)
    const int col0 = j2;
    const int col1 = j2 + 256;
    const int kbase = q * 64;

    // ---- one-time weight staging ----
    // wa[0..19] = col0 (k_local 0..39), wa[20..39] = col1 (k_local 0..39)
    u64 wa[2 * HELD_U64];
    {
        const ulonglong2* s0 = reinterpret_cast<const ulonglong2*>(W_hh + (size_t)col0 * HH + kbase);
        const ulonglong2* s1 = reinterpret_cast<const ulonglong2*>(W_hh + (size_t)col1 * HH + kbase);
        #pragma unroll
        for (int i = 0; i < HELD_U64 / 2; i++) {
            ulonglong2 a = s0[i]; wa[2*i] = a.x; wa[2*i+1] = a.y;
            ulonglong2 b = s1[i]; wa[HELD_U64 + 2*i] = b.x; wa[HELD_U64 + 2*i+1] = b.y;
        }
        // streamed region: k_local 40..63 (= 2*HELD_U64 floats in)
        const float4* t0 = reinterpret_cast<const float4*>(W_hh + (size_t)col0 * HH + kbase + 2 * HELD_U64);
        const float4* t1 = reinterpret_cast<const float4*>(W_hh + (size_t)col1 * HH + kbase + 2 * HELD_U64);
        #pragma unroll
        for (int i = 0; i < STR_QUADS; i++) {
            WS[i * 512 + tid] = t0[i];
            WS[(STR_QUADS + i) * 512 + tid] = t1[i];
        }
    }
    if (tid < 2 * HH) h_s[tid] = 0.f;

    // CTA loop bound: max length over its rows (lengths need not be sorted)
    int tlim;
    {
        int l0 = lengths[b0];
        int l1 = (NR == 2) ? lengths[b0 + 1] : l0;
        tlim = (l0 > l1) ? l0 : l1;
    }

    // ---- finalizer state: thread (j2<128, q<NR) owns (row=q, hc=j2) ----
    const bool exec = (j2 < 128) && (q < NR);
    const int hc = j2;
    const int r = q;
    const int len = exec ? lengths[b0 + r] : 0;
    float c_reg = 0.f, h_reg = 0.f;
    const float* gxp = g_gx + ((size_t)(b0 + r) * TT) * GG;
    float gxi = 0.f, gxf = 0.f, gxg = 0.f, gxo = 0.f;
    if (exec) {
        gxi = __ldg(gxp + hc);
        gxf = __ldg(gxp + HH + hc);
        gxg = __ldg(gxp + 2 * HH + hc);
        gxo = __ldg(gxp + 3 * HH + hc);
    }

    const ulonglong2* h2q = reinterpret_cast<const ulonglong2*>(h_s) + q * 16;
    const ulonglong2* WSu = reinterpret_cast<const ulonglong2*>(WS);
    const float* Pf = reinterpret_cast<const float*>(P);

    for (int t = 0; t < tlim; t++) {
        __syncthreads();   // S0: h_s(t-1) final, P(t-1) consumed

        // ---- phase A: partial dots over this thread's k-half ----
        u64 a00 = 0ull, a01 = 0ull, a10 = 0ull, a11 = 0ull;  // a[row][colpair]
        #pragma unroll
        for (int i = 0; i < HELD_U64 / 2; i++) {             // k_local 0..39
            ulonglong2 h0 = h2q[i];
            u64 wc0a = wa[2*i],             wc0b = wa[2*i + 1];
            u64 wc1a = wa[HELD_U64 + 2*i],  wc1b = wa[HELD_U64 + 2*i + 1];
            a00 = ffma2(wc0a, h0.x, a00); a00 = ffma2(wc0b, h0.y, a00);
            a01 = ffma2(wc1a, h0.x, a01); a01 = ffma2(wc1b, h0.y, a01);
            if (NR == 2) {
                ulonglong2 h1 = h2q[32 + i];
                a10 = ffma2(wc0a, h1.x, a10); a10 = ffma2(wc0b, h1.y, a10);
                a11 = ffma2(wc1a, h1.x, a11); a11 = ffma2(wc1b, h1.y, a11);
            }
        }
        #pragma unroll
        for (int i = 0; i < STR_QUADS; i++) {                // k_local 40..63
            ulonglong2 s0 = WSu[i * 512 + tid];
            ulonglong2 s1 = WSu[(STR_QUADS + i) * 512 + tid];
            ulonglong2 h0 = h2q[HELD_U64 / 2 + i];
            a00 = ffma2(s0.x, h0.x, a00); a00 = ffma2(s0.y, h0.y, a00);
            a01 = ffma2(s1.x, h0.x, a01); a01 = ffma2(s1.y, h0.y, a01);
            if (NR == 2) {
                ulonglong2 h1 = h2q[32 + HELD_U64 / 2 + i];
                a10 = ffma2(s0.x, h1.x, a10); a10 = ffma2(s0.y, h1.y, a10);
                a11 = ffma2(s1.x, h1.x, a11); a11 = ffma2(s1.y, h1.y, a11);
            }
        }
        float2 f00 = unpackf2(a00), f01 = unpackf2(a01);
        if (NR == 2) {
            float2 f10 = unpackf2(a10), f11 = unpackf2(a11);
            P[tid] = make_float4(f00.x + f00.y, f01.x + f01.y,
                                 f10.x + f10.y, f11.x + f11.y);
        } else {
            P[tid] = make_float4(f00.x + f00.y, f01.x + f01.y, 0.f, 0.f);
        }

        __syncthreads();   // S1: partials ready

        // ---- phase B: finalize + pointwise (warp-uniform branch) ----
        if (exec) {
            // own columns {hc, hc+256} = gates (i,g): both k-halves
            float2 pow0 = *reinterpret_cast<const float2*>(Pf + (hc)          * 4 + 2 * r);
            float2 pow1 = *reinterpret_cast<const float2*>(Pf + (256 + hc)    * 4 + 2 * r);
            // columns {hc+128, hc+384} = gates (f,o): both k-halves
            float2 pa   = *reinterpret_cast<const float2*>(Pf + (128 + hc)    * 4 + 2 * r);
            float2 pb   = *reinterpret_cast<const float2*>(Pf + (256 + 128 + hc) * 4 + 2 * r);
            float gi  = pow0.x + pow1.x + gxi;
            float ggv = pow0.y + pow1.y + gxg;
            float gf  = pa.x + pb.x + gxf;
            float go  = pa.y + pb.y + gxo;
            float i_ = sigmoidf_fast(gi);
            float f_ = sigmoidf_fast(gf);
            float g_ = tanhf_fast(ggv);
            float o_ = sigmoidf_fast(go);
            float cn = fmaf(f_, c_reg, i_ * g_);
            float hn = o_ * tanhf_fast(cn);
            bool m = (t < len);
            h_reg = m ? hn : h_reg;
            c_reg = m ? cn : c_reg;
            h_s[r * HH + hc] = h_reg;
            outs[((size_t)(b0 + r) * TT + t) * HH + hc] = m ? hn : 0.f;
            // prefetch gx(t+1) — hidden behind next phase A
            if (t + 1 < TT) {
                const float* gn = gxp + (size_t)(t + 1) * GG;
                gxi = __ldg(gn + hc);
                gxf = __ldg(gn + HH + hc);
                gxg = __ldg(gn + 2 * HH + hc);
                gxo = __ldg(gn + 3 * HH + hc);
            }
        }
    }

    if (exec) {
        h_out[(size_t)(b0 + r) * HH + hc] = h_reg;
        c_out[(size_t)(b0 + r) * HH + hc] = c_reg;
    }

    // ---- zero-fill outs tails: t in [len_r, TT) for each owned row ----
    #pragma unroll
    for (int rr = 0; rr < NR; rr++) {
        int lr = lengths[b0 + rr];
        int n4 = (TT - lr) * (HH / 4);
        float4* dst = reinterpret_cast<float4*>(
            outs + ((size_t)(b0 + rr) * TT + lr) * HH);
        float4 z = make_float4(0.f, 0.f, 0.f, 0.f);
        for (int i = tid; i < n4; i += 512) dst[i] = z;
    }
}

// Dispatcher: CTAs [0, n1) -> 1-row (rows 0..n1-1, the longest sequences);
// CTAs [n1, ...) -> 2-row (rows n1 + 2*(bi-n1), +1).
__global__ void __launch_bounds__(512, 1)
lstm_kernel(int n1,
            const float* __restrict__ W_hh,
            const int* __restrict__ lengths,
            float* __restrict__ outs,
            float* __restrict__ h_out,
            float* __restrict__ c_out) {
    extern __shared__ char smem[];
    int bi = blockIdx.x;
    if (bi < n1) {
        lstm_run<1>(bi, smem, W_hh, lengths, outs, h_out, c_out);
    } else {
        lstm_run<2>(n1 + (bi - n1) * 2, smem, W_hh, lengths, outs, h_out, c_out);
    }
}

// ---------------------------------------------------------------------------
// kernel_launch — graph-capturable: 4 launches on the default stream.
// Output: outputs[B,T,H] | h[1,B,H] | c[1,B,H] | embedded[B,T,E]
// ---------------------------------------------------------------------------
extern "C" void kernel_launch(void* const* d_in, const int* in_sizes, int n_in,
                              void* d_out, int out_size) {
    const int*   obs_ids     = (const int*)d_in[0];
    const int*   obs_slot    = (const int*)d_in[1];
    const int*   action_ids  = (const int*)d_in[2];
    const int*   is_action   = (const int*)d_in[3];
    const int*   lengths     = (const int*)d_in[4];
    const float* action_emb  = (const float*)d_in[5];
    const float* obs_emb     = (const float*)d_in[6];
    const float* W_ih        = (const float*)d_in[7];
    const float* W_hh        = (const float*)d_in[8];
    const float* b_ih        = (const float*)d_in[9];
    const float* b_hh        = (const float*)d_in[10];

    float* out   = (float*)d_out;
    float* outs  = out;                                    // B*T*H
    float* h_out = out + (size_t)BB * TT * HH;             // B*H
    float* c_out = h_out + (size_t)BB * HH;                // B*H
    float* emb   = c_out + (size_t)BB * HH;                // B*T*E

    cudaFuncSetAttribute(lstm_kernel,
                         cudaFuncAttributeMaxDynamicSharedMemorySize, SMEM_TOTAL);

    // choose n1 (number of 1-row CTAs) so total CTAs = 128 + n1/2 <= SM count
    int sms = 148;
    cudaDeviceGetAttribute(&sms, cudaDevAttrMultiProcessorCount, 0);
    int n1 = 2 * (sms - 128);
    if (n1 < 0) n1 = 0;
    if (n1 > 40) n1 = 40;
    n1 &= ~1;                          // even, so the 2-row region pairs cleanly
    int grid = n1 + (BB - n1) / 2;

    // 1) embedded = is_action ? action_emb[aid] : 0
    {
        int nthreads = BB * TT * 8;
        embed_init_kernel<<<nthreads / 256, 256>>>(action_ids, is_action,
                                                   action_emb, emb);
    }
    // 2) scatter-add observation embeddings into non-action slots
    {
        int n_obs = in_sizes[0];
        int nthreads = n_obs * 8;
        int blocks = (nthreads + 255) / 256;
        obs_scatter_kernel<<<blocks, 256>>>(obs_ids, obs_slot, is_action,
                                            obs_emb, emb, nthreads);
    }
    // 3) x-projection pre-GEMM: gx = bias + emb @ Wih^T  (262144 x 512)
    gatex_kernel<<<SLOTS / XCHUNK, 256>>>(emb, W_ih, b_ih, b_hh);

    // 4) persistent LSTM recurrence: one wave of (n1 + (256-n1)/2) CTAs
    lstm_kernel<<<grid, 512, SMEM_TOTAL>>>(n1, W_hh, lengths,
                                           outs, h_out, c_out);
}

// round 11
// speedup vs baseline: 1.6379x; 1.1392x over previous
#include <cuda_runtime.h>
#include <cuda_bf16.h>
#include <cuda_fp16.h>

// Problem constants (fixed by the reference)
#define BB 256
#define TT 1024
#define EE 32
#define HH 128
#define GG 512   // 4*H
#define SLOTS (BB * TT)

typedef unsigned long long u64;

// ---- f32x2 packed FMA (Blackwell FFMA2: only reachable via PTX) ----
__device__ __forceinline__ u64 ffma2(u64 a, u64 b, u64 c) {
    u64 d;
    asm("fma.rn.f32x2 %0, %1, %2, %3;" : "=l"(d) : "l"(a), "l"(b), "l"(c));
    return d;
}
__device__ __forceinline__ float2 unpackf2(u64 v) {
    float2 r;
    asm("mov.b64 {%0, %1}, %2;" : "=f"(r.x), "=f"(r.y) : "l"(v));
    return r;
}

__device__ __forceinline__ float sigmoidf_fast(float x) {
    return 1.0f / (1.0f + __expf(-x));
}
__device__ __forceinline__ float tanhf_fast(float x) {
    return 2.0f / (1.0f + __expf(-2.0f * x)) - 1.0f;
}

// 512 MB scratch: precomputed x-projection gate_x[slot][512] = bias + x.Wih^T
__device__ float g_gx[(size_t)SLOTS * GG];

// ---------------------------------------------------------------------------
// Kernel 1: embedded[b,t,:] = is_action ? action_emb[action_ids] : 0
// ---------------------------------------------------------------------------
__global__ void embed_init_kernel(const int* __restrict__ action_ids,
                                  const int* __restrict__ is_action,
                                  const float* __restrict__ action_emb,
                                  float* __restrict__ emb) {
    int gid = blockIdx.x * blockDim.x + threadIdx.x;   // BB*TT*8 threads
    int slot = gid >> 3;
    int e4 = gid & 7;
    float4 v = make_float4(0.f, 0.f, 0.f, 0.f);
    if (is_action[slot]) {
        int aid = action_ids[slot];
        v = reinterpret_cast<const float4*>(action_emb + (size_t)aid * EE)[e4];
    }
    reinterpret_cast<float4*>(emb)[gid] = v;
}

// ---------------------------------------------------------------------------
// Kernel 2: ragged embedding-bag scatter: emb[slot] += obs_emb[id] if !is_action
// ---------------------------------------------------------------------------
__global__ void obs_scatter_kernel(const int* __restrict__ obs_ids,
                                   const int* __restrict__ obs_slot,
                                   const int* __restrict__ is_action,
                                   const float* __restrict__ obs_emb,
                                   float* __restrict__ emb,
                                   int n_threads) {
    int gid = blockIdx.x * blockDim.x + threadIdx.x;
    if (gid >= n_threads) return;
    int i = gid >> 3;
    int e4 = gid & 7;
    int slot = obs_slot[i];
    if (!is_action[slot]) {
        int id = obs_ids[i];
        float4 v = reinterpret_cast<const float4*>(obs_emb + (size_t)id * EE)[e4];
        float* dst = emb + (size_t)slot * EE + e4 * 4;
        atomicAdd(dst + 0, v.x);
        atomicAdd(dst + 1, v.y);
        atomicAdd(dst + 2, v.z);
        atomicAdd(dst + 3, v.w);
    }
}

// ---------------------------------------------------------------------------
// Kernel 3: gate_x pre-GEMM. gx[slot][j] = (b_ih+b_hh)[j] + emb[slot,:].Wih[j,:]
// ---------------------------------------------------------------------------
#define XCHUNK 64
__global__ void __launch_bounds__(256, 2)
gatex_kernel(const float* __restrict__ emb, const float* __restrict__ W_ih,
             const float* __restrict__ b_ih, const float* __restrict__ b_hh) {
    __shared__ float xs[XCHUNK * EE];    // 8 KB
    const int tid = threadIdx.x;
    const int j0 = tid;
    const int j1 = tid + 256;

    u64 w0[16], w1[16];
    {
        const ulonglong2* s0 = reinterpret_cast<const ulonglong2*>(W_ih + (size_t)j0 * EE);
        const ulonglong2* s1 = reinterpret_cast<const ulonglong2*>(W_ih + (size_t)j1 * EE);
        #pragma unroll
        for (int i = 0; i < 8; i++) {
            ulonglong2 a = s0[i]; w0[2*i] = a.x; w0[2*i+1] = a.y;
            ulonglong2 b = s1[i]; w1[2*i] = b.x; w1[2*i+1] = b.y;
        }
    }
    const float bias0 = b_ih[j0] + b_hh[j0];
    const float bias1 = b_ih[j1] + b_hh[j1];

    const int base = blockIdx.x * XCHUNK;

    {
        const float4* src = reinterpret_cast<const float4*>(emb + (size_t)base * EE);
        reinterpret_cast<float4*>(xs)[tid] = src[tid];
        reinterpret_cast<float4*>(xs)[tid + 256] = src[tid + 256];
    }
    __syncthreads();

    #pragma unroll 2
    for (int s = 0; s < XCHUNK; s++) {
        const ulonglong2* xv = reinterpret_cast<const ulonglong2*>(xs + s * EE);
        u64 a0 = 0ull, a1 = 0ull;
        #pragma unroll
        for (int k4 = 0; k4 < 8; k4++) {
            ulonglong2 x = xv[k4];
            a0 = ffma2(w0[2*k4],     x.x, a0);
            a0 = ffma2(w0[2*k4 + 1], x.y, a0);
            a1 = ffma2(w1[2*k4],     x.x, a1);
            a1 = ffma2(w1[2*k4 + 1], x.y, a1);
        }
        float2 r0 = unpackf2(a0);
        float2 r1 = unpackf2(a1);
        size_t o = (size_t)(base + s) * GG;
        g_gx[o + j0] = bias0 + r0.x + r0.y;
        g_gx[o + j1] = bias1 + r1.x + r1.y;
    }
}

// ---------------------------------------------------------------------------
// Kernel 4: persistent LSTM recurrence.
// Grid = n1 1-row CTAs (longest rows 0..n1-1) + 2-row CTAs pairing
// rows (n1+p, 255-p) (long with short). 2-row CTAs run a joint loop to
// min(lenA,lenB), then a 1-row continuation to max(lenA,lenB) on the longer
// row only. Early exit everywhere; outs tails zero-filled.
//
// Phase A (GEMM), per thread (j2, q): columns {j2, j2+256}, k in [64q,64q+64):
//   k_local 0..39 in registers (20 u64/col), 40..63 streamed from smem
//   (12 LDS.128/step), h broadcast from smem (own k-half only).
// Phase B: thread (j2<128, q) finalizes (row slot q, hc=j2); c/h in regs.
// Exact fp32 everywhere.
// ---------------------------------------------------------------------------
#define HELD_U64  20             // u64 per col in regs (k_local 0..39)
#define STR_QUADS 6              // float4 per col streamed (k_local 40..63)

#define OFF_WS 0
#define SZ_WS  (2 * STR_QUADS * 512 * 16)    // 98304
#define OFF_H  (OFF_WS + SZ_WS)
#define SZ_H   (2 * HH * 4)                  // 1024
#define OFF_P  (OFF_H + SZ_H)
#define SZ_P   (512 * 16)                    // 8192
#define SMEM_TOTAL (OFF_P + SZ_P)            // 107520

// ---- shared weight staging (identical for all CTA flavors) ----
__device__ __forceinline__ void stage_weights(
    const float* __restrict__ W_hh, float4* WS, u64* wa,
    int tid, int col0, int col1, int kbase) {
    const ulonglong2* s0 = reinterpret_cast<const ulonglong2*>(W_hh + (size_t)col0 * HH + kbase);
    const ulonglong2* s1 = reinterpret_cast<const ulonglong2*>(W_hh + (size_t)col1 * HH + kbase);
    #pragma unroll
    for (int i = 0; i < HELD_U64 / 2; i++) {
        ulonglong2 a = s0[i]; wa[2*i] = a.x; wa[2*i+1] = a.y;
        ulonglong2 b = s1[i]; wa[HELD_U64 + 2*i] = b.x; wa[HELD_U64 + 2*i+1] = b.y;
    }
    const float4* t0 = reinterpret_cast<const float4*>(W_hh + (size_t)col0 * HH + kbase + 2 * HELD_U64);
    const float4* t1 = reinterpret_cast<const float4*>(W_hh + (size_t)col1 * HH + kbase + 2 * HELD_U64);
    #pragma unroll
    for (int i = 0; i < STR_QUADS; i++) {
        WS[i * 512 + tid] = t0[i];
        WS[(STR_QUADS + i) * 512 + tid] = t1[i];
    }
}

// ---- 1-row phase A partials for row slot `slot` (0 or 1); writes P[tid].xy
__device__ __forceinline__ void phaseA_1row(
    const u64* wa, const ulonglong2* WSu, const ulonglong2* h2,
    float4* P, int tid, int q, int slot) {
    const ulonglong2* hq = h2 + slot * 32 + q * 16;
    u64 a0 = 0ull, a1 = 0ull;
    #pragma unroll
    for (int i = 0; i < HELD_U64 / 2; i++) {
        ulonglong2 h0 = hq[i];
        a0 = ffma2(wa[2*i], h0.x, a0);             a0 = ffma2(wa[2*i+1], h0.y, a0);
        a1 = ffma2(wa[HELD_U64 + 2*i], h0.x, a1);  a1 = ffma2(wa[HELD_U64 + 2*i+1], h0.y, a1);
    }
    #pragma unroll
    for (int i = 0; i < STR_QUADS; i++) {
        ulonglong2 s0 = WSu[i * 512 + tid];
        ulonglong2 s1 = WSu[(STR_QUADS + i) * 512 + tid];
        ulonglong2 h0 = hq[HELD_U64 / 2 + i];
        a0 = ffma2(s0.x, h0.x, a0); a0 = ffma2(s0.y, h0.y, a0);
        a1 = ffma2(s1.x, h0.x, a1); a1 = ffma2(s1.y, h0.y, a1);
    }
    float2 f0 = unpackf2(a0), f1 = unpackf2(a1);
    P[tid] = make_float4(f0.x + f0.y, f1.x + f1.y, 0.f, 0.f);
}

// ---- 1-row CTA: processes `row` to lengths[row] ----
__device__ __forceinline__ void lstm_run1(
    int row, char* smem,
    const float* __restrict__ W_hh, const int* __restrict__ lengths,
    float* __restrict__ outs, float* __restrict__ h_out,
    float* __restrict__ c_out) {

    float4* WS  = reinterpret_cast<float4*>(smem + OFF_WS);
    float*  h_s = reinterpret_cast<float*>(smem + OFF_H);
    float4* P   = reinterpret_cast<float4*>(smem + OFF_P);

    const int tid = threadIdx.x;
    const int j2  = tid & 255;
    const int q   = tid >> 8;

    u64 wa[2 * HELD_U64];
    stage_weights(W_hh, WS, wa, tid, j2, j2 + 256, q * 64);
    if (tid < 2 * HH) h_s[tid] = 0.f;

    const int len = lengths[row];
    const bool exec = (j2 < 128) && (q == 0);
    const int hc = j2;
    float c_reg = 0.f, h_reg = 0.f;
    const float* gxp = g_gx + ((size_t)row * TT) * GG;
    float gxi = 0.f, gxf = 0.f, gxg = 0.f, gxo = 0.f;
    if (exec) {
        gxi = __ldg(gxp + hc);
        gxf = __ldg(gxp + HH + hc);
        gxg = __ldg(gxp + 2 * HH + hc);
        gxo = __ldg(gxp + 3 * HH + hc);
    }

    const ulonglong2* h2 = reinterpret_cast<const ulonglong2*>(h_s);
    const ulonglong2* WSu = reinterpret_cast<const ulonglong2*>(WS);
    const float* Pf = reinterpret_cast<const float*>(P);

    for (int t = 0; t < len; t++) {
        __syncthreads();
        phaseA_1row(wa, WSu, h2, P, tid, q, 0);
        __syncthreads();
        if (exec) {
            float2 pow0 = *reinterpret_cast<const float2*>(Pf + (hc) * 4);
            float2 pow1 = *reinterpret_cast<const float2*>(Pf + (256 + hc) * 4);
            float2 pa   = *reinterpret_cast<const float2*>(Pf + (128 + hc) * 4);
            float2 pb   = *reinterpret_cast<const float2*>(Pf + (384 + hc) * 4);
            float gi  = pow0.x + pow1.x + gxi;
            float ggv = pow0.y + pow1.y + gxg;
            float gf  = pa.x + pb.x + gxf;
            float go  = pa.y + pb.y + gxo;
            float i_ = sigmoidf_fast(gi);
            float f_ = sigmoidf_fast(gf);
            float g_ = tanhf_fast(ggv);
            float o_ = sigmoidf_fast(go);
            float cn = fmaf(f_, c_reg, i_ * g_);
            float hn = o_ * tanhf_fast(cn);
            h_reg = hn; c_reg = cn;                 // t < len always here
            h_s[hc] = hn;
            outs[((size_t)row * TT + t) * HH + hc] = hn;
            if (t + 1 < TT) {
                const float* gn = gxp + (size_t)(t + 1) * GG;
                gxi = __ldg(gn + hc);
                gxf = __ldg(gn + HH + hc);
                gxg = __ldg(gn + 2 * HH + hc);
                gxo = __ldg(gn + 3 * HH + hc);
            }
        }
    }

    if (exec) {
        h_out[(size_t)row * HH + hc] = h_reg;
        c_out[(size_t)row * HH + hc] = c_reg;
    }
    // zero-fill tail
    {
        int n4 = (TT - len) * (HH / 4);
        float4* dst = reinterpret_cast<float4*>(outs + ((size_t)row * TT + len) * HH);
        float4 z = make_float4(0.f, 0.f, 0.f, 0.f);
        for (int i = tid; i < n4; i += 512) dst[i] = z;
    }
}

// ---- 2-row CTA: rows rA (slot 0), rB (slot 1); joint loop to min, then
//      1-row continuation on the longer row ----
__device__ __forceinline__ void lstm_run2(
    int rA, int rB, char* smem,
    const float* __restrict__ W_hh, const int* __restrict__ lengths,
    float* __restrict__ outs, float* __restrict__ h_out,
    float* __restrict__ c_out) {

    float4* WS  = reinterpret_cast<float4*>(smem + OFF_WS);
    float*  h_s = reinterpret_cast<float*>(smem + OFF_H);
    float4* P   = reinterpret_cast<float4*>(smem + OFF_P);

    const int tid = threadIdx.x;
    const int j2  = tid & 255;
    const int q   = tid >> 8;

    u64 wa[2 * HELD_U64];
    stage_weights(W_hh, WS, wa, tid, j2, j2 + 256, q * 64);
    if (tid < 2 * HH) h_s[tid] = 0.f;

    const int lenA = lengths[rA];
    const int lenB = lengths[rB];
    const int lmin = (lenA < lenB) ? lenA : lenB;
    const int lmax = (lenA < lenB) ? lenB : lenA;
    const int qlong = (lenA >= lenB) ? 0 : 1;

    // finalizer: thread (j2<128, q) owns (row slot q, hc=j2)
    const bool exec = (j2 < 128);
    const int hc = j2;
    const int myrow = q ? rB : rA;
    float c_reg = 0.f, h_reg = 0.f;
    const float* gxp = g_gx + ((size_t)myrow * TT) * GG;
    float gxi = 0.f, gxf = 0.f, gxg = 0.f, gxo = 0.f;
    if (exec) {
        gxi = __ldg(gxp + hc);
        gxf = __ldg(gxp + HH + hc);
        gxg = __ldg(gxp + 2 * HH + hc);
        gxo = __ldg(gxp + 3 * HH + hc);
    }

    const ulonglong2* h2 = reinterpret_cast<const ulonglong2*>(h_s);
    const ulonglong2* h2q = h2 + q * 16;
    const ulonglong2* WSu = reinterpret_cast<const ulonglong2*>(WS);
    const float* Pf = reinterpret_cast<const float*>(P);

    // ---- joint loop: both rows active (t < lmin <= both lens) ----
    for (int t = 0; t < lmin; t++) {
        __syncthreads();
        u64 a00 = 0ull, a01 = 0ull, a10 = 0ull, a11 = 0ull;
        #pragma unroll
        for (int i = 0; i < HELD_U64 / 2; i++) {
            ulonglong2 h0 = h2q[i];
            ulonglong2 h1 = h2q[32 + i];
            u64 wc0a = wa[2*i],            wc0b = wa[2*i + 1];
            u64 wc1a = wa[HELD_U64 + 2*i], wc1b = wa[HELD_U64 + 2*i + 1];
            a00 = ffma2(wc0a, h0.x, a00); a00 = ffma2(wc0b, h0.y, a00);
            a01 = ffma2(wc1a, h0.x, a01); a01 = ffma2(wc1b, h0.y, a01);
            a10 = ffma2(wc0a, h1.x, a10); a10 = ffma2(wc0b, h1.y, a10);
            a11 = ffma2(wc1a, h1.x, a11); a11 = ffma2(wc1b, h1.y, a11);
        }
        #pragma unroll
        for (int i = 0; i < STR_QUADS; i++) {
            ulonglong2 s0 = WSu[i * 512 + tid];
            ulonglong2 s1 = WSu[(STR_QUADS + i) * 512 + tid];
            ulonglong2 h0 = h2q[HELD_U64 / 2 + i];
            ulonglong2 h1 = h2q[32 + HELD_U64 / 2 + i];
            a00 = ffma2(s0.x, h0.x, a00); a00 = ffma2(s0.y, h0.y, a00);
            a01 = ffma2(s1.x, h0.x, a01); a01 = ffma2(s1.y, h0.y, a01);
            a10 = ffma2(s0.x, h1.x, a10); a10 = ffma2(s0.y, h1.y, a10);
            a11 = ffma2(s1.x, h1.x, a11); a11 = ffma2(s1.y, h1.y, a11);
        }
        float2 f00 = unpackf2(a00), f01 = unpackf2(a01);
        float2 f10 = unpackf2(a10), f11 = unpackf2(a11);
        P[tid] = make_float4(f00.x + f00.y, f01.x + f01.y,
                             f10.x + f10.y, f11.x + f11.y);

        __syncthreads();

        if (exec) {
            float2 pow0 = *reinterpret_cast<const float2*>(Pf + (hc) * 4 + 2 * q);
            float2 pow1 = *reinterpret_cast<const float2*>(Pf + (256 + hc) * 4 + 2 * q);
            float2 pa   = *reinterpret_cast<const float2*>(Pf + (128 + hc) * 4 + 2 * q);
            float2 pb   = *reinterpret_cast<const float2*>(Pf + (384 + hc) * 4 + 2 * q);
            float gi  = pow0.x + pow1.x + gxi;
            float ggv = pow0.y + pow1.y + gxg;
            float gf  = pa.x + pb.x + gxf;
            float go  = pa.y + pb.y + gxo;
            float i_ = sigmoidf_fast(gi);
            float f_ = sigmoidf_fast(gf);
            float g_ = tanhf_fast(ggv);
            float o_ = sigmoidf_fast(go);
            float cn = fmaf(f_, c_reg, i_ * g_);
            float hn = o_ * tanhf_fast(cn);
            h_reg = hn; c_reg = cn;                 // t < lmin <= len here
            h_s[q * HH + hc] = hn;
            outs[((size_t)myrow * TT + t) * HH + hc] = hn;
            if (t + 1 < TT) {
                const float* gn = gxp + (size_t)(t + 1) * GG;
                gxi = __ldg(gn + hc);
                gxf = __ldg(gn + HH + hc);
                gxg = __ldg(gn + 2 * HH + hc);
                gxo = __ldg(gn + 3 * HH + hc);
            }
        }
    }

    // ---- continuation: only the longer row (slot qlong) ----
    const int rowL = qlong ? rB : rA;
    for (int t = lmin; t < lmax; t++) {
        __syncthreads();
        phaseA_1row(wa, WSu, h2, P, tid, q, qlong);
        __syncthreads();
        if (exec && q == qlong) {
            float2 pow0 = *reinterpret_cast<const float2*>(Pf + (hc) * 4);
            float2 pow1 = *reinterpret_cast<const float2*>(Pf + (256 + hc) * 4);
            float2 pa   = *reinterpret_cast<const float2*>(Pf + (128 + hc) * 4);
            float2 pb   = *reinterpret_cast<const float2*>(Pf + (384 + hc) * 4);
            float gi  = pow0.x + pow1.x + gxi;
            float ggv = pow0.y + pow1.y + gxg;
            float gf  = pa.x + pb.x + gxf;
            float go  = pa.y + pb.y + gxo;
            float i_ = sigmoidf_fast(gi);
            float f_ = sigmoidf_fast(gf);
            float g_ = tanhf_fast(ggv);
            float o_ = sigmoidf_fast(go);
            float cn = fmaf(f_, c_reg, i_ * g_);
            float hn = o_ * tanhf_fast(cn);
            h_reg = hn; c_reg = cn;                 // t < lmax == lengths[rowL]
            h_s[qlong * HH + hc] = hn;
            outs[((size_t)rowL * TT + t) * HH + hc] = hn;
            if (t + 1 < TT) {
                const float* gn = gxp + (size_t)(t + 1) * GG;
                gxi = __ldg(gn + hc);
                gxf = __ldg(gn + HH + hc);
                gxg = __ldg(gn + 2 * HH + hc);
                gxo = __ldg(gn + 3 * HH + hc);
            }
        }
    }

    if (exec) {
        h_out[(size_t)myrow * HH + hc] = h_reg;
        c_out[(size_t)myrow * HH + hc] = c_reg;
    }
    // zero-fill tails for both rows
    {
        int n4 = (TT - lenA) * (HH / 4);
        float4* dst = reinterpret_cast<float4*>(outs + ((size_t)rA * TT + lenA) * HH);
        float4 z = make_float4(0.f, 0.f, 0.f, 0.f);
        for (int i = tid; i < n4; i += 512) dst[i] = z;
        n4 = (TT - lenB) * (HH / 4);
        dst = reinterpret_cast<float4*>(outs + ((size_t)rB * TT + lenB) * HH);
        for (int i = tid; i < n4; i += 512) dst[i] = z;
    }
}

// Dispatcher: CTAs [0,n1) -> 1-row (rows 0..n1-1, longest);
// CTA n1+p -> 2-row pair (n1+p, BB-1-p) (long paired with short).
__global__ void __launch_bounds__(512, 1)
lstm_kernel(int n1,
            const float* __restrict__ W_hh,
            const int* __restrict__ lengths,
            float* __restrict__ outs,
            float* __restrict__ h_out,
            float* __restrict__ c_out) {
    extern __shared__ char smem[];
    int bi = blockIdx.x;
    if (bi < n1) {
        lstm_run1(bi, smem, W_hh, lengths, outs, h_out, c_out);
    } else {
        int p = bi - n1;
        lstm_run2(n1 + p, BB - 1 - p, smem, W_hh, lengths, outs, h_out, c_out);
    }
}

// ---------------------------------------------------------------------------
// kernel_launch — graph-capturable: 4 launches on the default stream.
// Output: outputs[B,T,H] | h[1,B,H] | c[1,B,H] | embedded[B,T,E]
// ---------------------------------------------------------------------------
extern "C" void kernel_launch(void* const* d_in, const int* in_sizes, int n_in,
                              void* d_out, int out_size) {
    const int*   obs_ids     = (const int*)d_in[0];
    const int*   obs_slot    = (const int*)d_in[1];
    const int*   action_ids  = (const int*)d_in[2];
    const int*   is_action   = (const int*)d_in[3];
    const int*   lengths     = (const int*)d_in[4];
    const float* action_emb  = (const float*)d_in[5];
    const float* obs_emb     = (const float*)d_in[6];
    const float* W_ih        = (const float*)d_in[7];
    const float* W_hh        = (const float*)d_in[8];
    const float* b_ih        = (const float*)d_in[9];
    const float* b_hh        = (const float*)d_in[10];

    float* out   = (float*)d_out;
    float* outs  = out;                                    // B*T*H
    float* h_out = out + (size_t)BB * TT * HH;             // B*H
    float* c_out = h_out + (size_t)BB * HH;                // B*H
    float* emb   = c_out + (size_t)BB * HH;                // B*T*E

    cudaFuncSetAttribute(lstm_kernel,
                         cudaFuncAttributeMaxDynamicSharedMemorySize, SMEM_TOTAL);

    // n1 1-row CTAs for the longest rows; total CTAs = n1 + (256-n1)/2 <= SMs
    int sms = 148;
    cudaDeviceGetAttribute(&sms, cudaDevAttrMultiProcessorCount, 0);
    int n1 = 2 * (sms - 128);
    if (n1 < 0) n1 = 0;
    if (n1 > 40) n1 = 40;
    n1 &= ~1;
    int grid = n1 + (BB - n1) / 2;

    // 1) embedded = is_action ? action_emb[aid] : 0
    {
        int nthreads = BB * TT * 8;
        embed_init_kernel<<<nthreads / 256, 256>>>(action_ids, is_action,
                                                   action_emb, emb);
    }
    // 2) scatter-add observation embeddings into non-action slots
    {
        int n_obs = in_sizes[0];
        int nthreads = n_obs * 8;
        int blocks = (nthreads + 255) / 256;
        obs_scatter_kernel<<<blocks, 256>>>(obs_ids, obs_slot, is_action,
                                            obs_emb, emb, nthreads);
    }
    // 3) x-projection pre-GEMM: gx = bias + emb @ Wih^T  (262144 x 512)
    gatex_kernel<<<SLOTS / XCHUNK, 256>>>(emb, W_ih, b_ih, b_hh);

    // 4) persistent LSTM recurrence: one wave, long/short pairing
    lstm_kernel<<<grid, 512, SMEM_TOTAL>>>(n1, W_hh, lengths,
                                           outs, h_out, c_out);
}